// round 9
// baseline (speedup 1.0000x reference)
#include <cuda_runtime.h>
#include <stdint.h>

// Problem shape is fixed by setup_inputs(): B=64, N=4, H=512, W=512, num=1024.
#define BB 64
#define NPLANES 4
#define HH 512
#define WW 512
#define HWPIX (HH * WW)            // 262144
#define HW4 (HWPIX / 4)            // 65536 float4s per plane
#define WORDS_PER_B (HWPIX / 32)   // 8192
#define CHUNKS 256                 // coarse chunks per batch (32 words each)
#define NUM 1024
#define IDX_ELEMS (BB * NUM * 2)   // 131072 index values
#define PARTS 4                    // sample blocks per batch

// Scratch (no allocations allowed).
__device__ uint32_t g_bits[BB * WORDS_PER_B];    // 2 MiB  packed valid bits
__device__ int      g_csum[BB * WORDS_PER_B];    // 2 MiB  bits before word w
__device__ int      g_coarse[BB * CHUNKS];       // 64 KiB bits before chunk c
__device__ int      g_cnt[BB];

// ---------------------------------------------------------------------------
// Kernel 1: valid[b,p] = (sum_n masks[b,n,p]) > 0.5, packed 32 pixels/word.
// 4 consecutive pixels per thread via float4 loads. Measured ~6.7 TB/s
// effective — at the LTS/DRAM cap; unchanged.
// ---------------------------------------------------------------------------
__global__ __launch_bounds__(256) void k_mask_bits(const float4* __restrict__ m4) {
    int gid4 = blockIdx.x * 256 + threadIdx.x;   // float4 index in [0, B*HW/4)
    int b  = gid4 >> 16;                         // (gid4*4) / HWPIX
    int p4 = gid4 & (HW4 - 1);
    const float4* base = m4 + (size_t)b * NPLANES * HW4 + p4;
    float4 a0 = base[0];
    float4 a1 = base[HW4];
    float4 a2 = base[2 * HW4];
    float4 a3 = base[3 * HW4];
    // Keep the exact association order that validated bit-exact.
    float sx = ((a0.x + a1.x) + a2.x) + a3.x;
    float sy = ((a0.y + a1.y) + a2.y) + a3.y;
    float sz = ((a0.z + a1.z) + a2.z) + a3.z;
    float sw = ((a0.w + a1.w) + a2.w) + a3.w;
    unsigned nib = (unsigned)(sx > 0.5f)
                 | ((unsigned)(sy > 0.5f) << 1)
                 | ((unsigned)(sz > 0.5f) << 2)
                 | ((unsigned)(sw > 0.5f) << 3);
    int l = threadIdx.x & 31;
    unsigned v = nib << ((l & 7) * 4);
    v |= __shfl_xor_sync(0xFFFFFFFFu, v, 1);
    v |= __shfl_xor_sync(0xFFFFFFFFu, v, 2);
    v |= __shfl_xor_sync(0xFFFFFFFFu, v, 4);
    if ((l & 7) == 0) g_bits[gid4 >> 3] = v;     // word = (4*gid4)/32
}

// ---------------------------------------------------------------------------
// Kernel 2: per-batch scan, ONCE (64 blocks x 256 threads). Warp-shuffle scan
// (2 barriers). Emits word-level csum, chunk-level coarse csum, batch total.
// ---------------------------------------------------------------------------
__global__ __launch_bounds__(256) void k_scan() {
    __shared__ int warp_tot[8];
    int b = blockIdx.x;
    int t = threadIdx.x;
    int lane = t & 31, wid = t >> 5;

    const uint4* bits4 = reinterpret_cast<const uint4*>(g_bits + (size_t)b * WORDS_PER_B);
    int local[32];
    int acc = 0;
#pragma unroll
    for (int i = 0; i < 8; i++) {
        uint4 w = bits4[t * 8 + i];
        local[i * 4 + 0] = __popc(w.x);
        local[i * 4 + 1] = __popc(w.y);
        local[i * 4 + 2] = __popc(w.z);
        local[i * 4 + 3] = __popc(w.w);
        acc += local[i * 4 + 0] + local[i * 4 + 1] + local[i * 4 + 2] + local[i * 4 + 3];
    }
    // Warp-inclusive scan of per-thread totals.
    int v = acc;
#pragma unroll
    for (int off = 1; off < 32; off <<= 1) {
        int n = __shfl_up_sync(0xFFFFFFFFu, v, off);
        if (lane >= off) v += n;
    }
    if (lane == 31) warp_tot[wid] = v;
    __syncthreads();
    int wbase = 0;
#pragma unroll
    for (int i = 0; i < 8; i++) wbase += (i < wid) ? warp_tot[i] : 0;

    int excl = wbase + v - acc;          // bits strictly before this thread's chunk
    g_coarse[b * CHUNKS + t] = excl;
    int run = excl;
    int* cs = g_csum + (size_t)b * WORDS_PER_B + t * 32;
#pragma unroll
    for (int i = 0; i < 32; i++) {
        cs[i] = run;                     // bits strictly before word (t*32 + i)
        run += local[i];
    }
    if (t == 255) g_cnt[b] = run;        // inclusive total of last chunk = batch total
}

// ---------------------------------------------------------------------------
// Kernel 3: sampling, 1 point per thread, tiny smem (1KB coarse stage).
// Coarse 8-level search in shared, fine 5-level search within one 128-byte
// span of g_csum (L2/L1), 5-step popcount select of the k-th set bit.
// Replicates: r = min(int(u * float(cnt)), cnt-1); pos = searchsorted(csum, r+1).
// ---------------------------------------------------------------------------
__global__ __launch_bounds__(256) void k_sample(const float* __restrict__ rand_u,
                                                float* __restrict__ out,
                                                int tail_n) {
    __shared__ int s_coarse[CHUNKS];     // 1 KiB
    __shared__ int s_total;
    int b    = blockIdx.x >> 2;
    int part = blockIdx.x & (PARTS - 1);
    int t = threadIdx.x;

    s_coarse[t] = g_coarse[b * CHUNKS + t];
    if (t == 0) s_total = g_cnt[b];
    __syncthreads();

    int total = s_total;
    int pt = part * 256 + t;
    float u = rand_u[b * NUM + pt];

    int pos;
    if (total == 0) {
        // reference: cnt = max(total,1) = 1, r = 0, searchsorted over
        // all-zero csum for target 1 -> insertion point HW.
        pos = HWPIX;
    } else {
        int cnt = total;
        int r = (int)(u * (float)cnt);       // fp32 RN mul, trunc — matches jnp
        if (r > cnt - 1) r = cnt - 1;
        int tgt = r + 1;                     // want the tgt-th set bit (1-indexed)

        // Coarse: last chunk c with (bits before chunk) < tgt. s_coarse[0]=0<tgt.
        int lo = 0, hi = CHUNKS;
#pragma unroll
        for (int s = 0; s < 8; s++) {
            int mid = (lo + hi) >> 1;
            if (s_coarse[mid] < tgt) lo = mid; else hi = mid;
        }
        // Fine: last word w in [lo*32, lo*32+32) with csum[w] < tgt.
        const int* cs = g_csum + (size_t)b * WORDS_PER_B;
        int wlo = lo * 32, whi = wlo + 32;
#pragma unroll
        for (int s = 0; s < 5; s++) {
            int mid = (wlo + whi) >> 1;
            if (__ldg(cs + mid) < tgt) wlo = mid; else whi = mid;
        }
        uint32_t wrd = g_bits[(size_t)b * WORDS_PER_B + wlo];
        int k = tgt - __ldg(cs + wlo);       // k-th set bit inside word, k>=1
        // Fixed-depth 5-step binary select of the k-th set bit (1-indexed).
        int idx = 0;
        int c = __popc(wrd & 0xFFFFu);
        if (k > c) { k -= c; idx += 16; wrd >>= 16; }
        c = __popc(wrd & 0xFFu);
        if (k > c) { k -= c; idx += 8; wrd >>= 8; }
        c = __popc(wrd & 0xFu);
        if (k > c) { k -= c; idx += 4; wrd >>= 4; }
        c = __popc(wrd & 0x3u);
        if (k > c) { k -= c; idx += 2; wrd >>= 2; }
        c = wrd & 1u;
        if (k > c) { idx += 1; }
        pos = wlo * 32 + idx;
    }

    float2 hw;
    hw.x = (float)(pos / WW);
    hw.y = (float)(pos & (WW - 1));
    *reinterpret_cast<float2*>(out + ((size_t)b * NUM + pt) * 2) = hw;

    // Tail fill ((H, W) tuple leaves flattened into d_out).
    if (blockIdx.x == 0) {
        for (int i = t; i < tail_n; i += 256) out[IDX_ELEMS + i] = 512.0f;
    }
}

extern "C" void kernel_launch(void* const* d_in, const int* in_sizes, int n_in,
                              void* d_out, int out_size) {
    // Identify inputs by size, robust to metadata ordering.
    const float* masks  = nullptr;   // [64,4,512,512] f32 -> 67,108,864 elems
    const float* rand_u = nullptr;   // [64,1024] f32      -> 65,536 elems
    for (int i = 0; i < n_in; i++) {
        if (in_sizes[i] == BB * NPLANES * HWPIX) masks = (const float*)d_in[i];
        else if (in_sizes[i] == BB * NUM)        rand_u = (const float*)d_in[i];
    }
    if (!masks)  masks  = (const float*)d_in[0];
    if (!rand_u) rand_u = (const float*)d_in[1];
    float* out = (float*)d_out;      // [64,1024,2] stored as float32 (+ tail)

    int tail_n = out_size - IDX_ELEMS;
    if (tail_n < 0) tail_n = 0;

    k_mask_bits<<<(BB * HW4) / 256, 256>>>(reinterpret_cast<const float4*>(masks));
    k_scan<<<BB, 256>>>();
    k_sample<<<BB * PARTS, 256>>>(rand_u, out, tail_n);
}

// round 10
// speedup vs baseline: 1.1558x; 1.1558x over previous
#include <cuda_runtime.h>
#include <stdint.h>

// Problem shape is fixed by setup_inputs(): B=64, N=4, H=512, W=512, num=1024.
#define BB 64
#define NPLANES 4
#define HH 512
#define WW 512
#define HWPIX (HH * WW)            // 262144
#define HW4 (HWPIX / 4)            // 65536 float4s per plane
#define WORDS_PER_B (HWPIX / 32)   // 8192
#define CHUNKS 256                 // chunks per batch; chunk = 32 words = 1024 px
#define NUM 1024
#define IDX_ELEMS (BB * NUM * 2)   // 131072 index values
#define PARTS 4                    // sample blocks per batch

// Scratch (no allocations allowed).
__device__ uint32_t g_bits[BB * WORDS_PER_B];    // 2 MiB  packed valid bits
__device__ int      g_chunk[BB * CHUNKS];        // 64 KiB popcount per chunk

// ---------------------------------------------------------------------------
// Kernel 1: valid[b,p] = (sum_n masks[b,n,p]) > 0.5, packed 32 pixels/word.
// 4 consecutive pixels/thread via float4 (measured 6.66 TB/s, 84% DRAM — at
// the LTS cap). Each block covers exactly one 1024-pixel chunk, so it also
// block-reduces its popcount and emits g_chunk[blockIdx.x] — scan input for
// free, removing the separate scan kernel and the 4 MB csum round-trip.
// ---------------------------------------------------------------------------
__global__ __launch_bounds__(256) void k_mask_bits(const float4* __restrict__ m4) {
    int gid4 = blockIdx.x * 256 + threadIdx.x;   // float4 index in [0, B*HW/4)
    int b  = gid4 >> 16;                         // (gid4*4) / HWPIX
    int p4 = gid4 & (HW4 - 1);
    const float4* base = m4 + (size_t)b * NPLANES * HW4 + p4;
    float4 a0 = base[0];
    float4 a1 = base[HW4];
    float4 a2 = base[2 * HW4];
    float4 a3 = base[3 * HW4];
    // Keep the exact association order that validated bit-exact.
    float sx = ((a0.x + a1.x) + a2.x) + a3.x;
    float sy = ((a0.y + a1.y) + a2.y) + a3.y;
    float sz = ((a0.z + a1.z) + a2.z) + a3.z;
    float sw = ((a0.w + a1.w) + a2.w) + a3.w;
    unsigned nib = (unsigned)(sx > 0.5f)
                 | ((unsigned)(sy > 0.5f) << 1)
                 | ((unsigned)(sz > 0.5f) << 2)
                 | ((unsigned)(sw > 0.5f) << 3);
    int l = threadIdx.x & 31;
    unsigned v = nib << ((l & 7) * 4);
    v |= __shfl_xor_sync(0xFFFFFFFFu, v, 1);
    v |= __shfl_xor_sync(0xFFFFFFFFu, v, 2);
    v |= __shfl_xor_sync(0xFFFFFFFFu, v, 4);
    if ((l & 7) == 0) g_bits[gid4 >> 3] = v;     // word = (4*gid4)/32

    // Chunk popcount: block-wide sum of per-thread nibble popcounts.
    __shared__ int wsum[8];
    int c4 = __popc(nib);
#pragma unroll
    for (int off = 16; off; off >>= 1)
        c4 += __shfl_xor_sync(0xFFFFFFFFu, c4, off);
    if (l == 0) wsum[threadIdx.x >> 5] = c4;
    __syncthreads();
    if (threadIdx.x == 0) {
        int s = 0;
#pragma unroll
        for (int i = 0; i < 8; i++) s += wsum[i];
        g_chunk[blockIdx.x] = s;                 // blockIdx.x = b*CHUNKS + chunk
    }
}

// ---------------------------------------------------------------------------
// Kernel 2: sampling. PARTS blocks per batch, 1 point per thread.
// In-block warp-shuffle scan of the 256 chunk counts -> coarse csum in shared
// (1 KB, L2-hot input). Coarse 8-level search in shared, then select the k-th
// set bit inside the 1024-pixel chunk from its 128 B of bits (8x uint4,
// MLP=8, L2) via flagged unrolled popcount selection — no dependent global
// binary-search chain.
// Replicates: r = min(int(u * float(cnt)), cnt-1); pos = searchsorted(csum, r+1).
// ---------------------------------------------------------------------------
__global__ __launch_bounds__(256) void k_sample(const float* __restrict__ rand_u,
                                                float* __restrict__ out,
                                                int tail_n) {
    __shared__ int s_coarse[CHUNKS];     // exclusive csum of chunk counts
    __shared__ int warp_tot[8];
    __shared__ int s_total;
    int b    = blockIdx.x >> 2;
    int part = blockIdx.x & (PARTS - 1);
    int t = threadIdx.x;
    int lane = t & 31, wid = t >> 5;

    // Scan 256 chunk counts (one per thread).
    int c = g_chunk[b * CHUNKS + t];
    int v = c;
#pragma unroll
    for (int off = 1; off < 32; off <<= 1) {
        int n = __shfl_up_sync(0xFFFFFFFFu, v, off);
        if (lane >= off) v += n;
    }
    if (lane == 31) warp_tot[wid] = v;
    __syncthreads();
    int wbase = 0;
#pragma unroll
    for (int i = 0; i < 8; i++) wbase += (i < wid) ? warp_tot[i] : 0;
    s_coarse[t] = wbase + v - c;         // bits strictly before chunk t
    if (t == 255) s_total = wbase + v;   // batch total
    __syncthreads();

    int total = s_total;
    int pt = part * 256 + t;
    float u = rand_u[b * NUM + pt];

    int pos;
    if (total == 0) {
        // reference: cnt = max(total,1) = 1, r = 0, searchsorted over
        // all-zero csum for target 1 -> insertion point HW.
        pos = HWPIX;
    } else {
        int cnt = total;
        int r = (int)(u * (float)cnt);       // fp32 RN mul, trunc — matches jnp
        if (r > cnt - 1) r = cnt - 1;
        int tgt = r + 1;                     // want the tgt-th set bit (1-indexed)

        // Coarse: last chunk with (bits before chunk) < tgt. s_coarse[0]=0<tgt.
        int lo = 0, hi = CHUNKS;
#pragma unroll
        for (int s = 0; s < 8; s++) {
            int mid = (lo + hi) >> 1;
            if (s_coarse[mid] < tgt) lo = mid; else hi = mid;
        }
        int k = tgt - s_coarse[lo];          // k-th set bit within chunk, k>=1

        // Load the chunk's 32 bit-words (128 B) and select group of 4 words.
        const uint4* bw = reinterpret_cast<const uint4*>(
            g_bits + (size_t)b * WORDS_PER_B + lo * 32);
        int gi = 0;
        bool found = false;
#pragma unroll
        for (int i = 0; i < 8; i++) {
            uint4 q = bw[i];
            int gs = __popc(q.x) + __popc(q.y) + __popc(q.z) + __popc(q.w);
            if (!found) {
                if (k > gs) k -= gs;
                else { gi = i; found = true; }
            }
        }
        // Word within the group (re-load: L1 hit).
        uint4 qq = bw[gi];
        int w2 = 0;
        uint32_t wrd = qq.x;
        int pc = __popc(qq.x);
        if (k > pc) {
            k -= pc; wrd = qq.y; w2 = 1; pc = __popc(qq.y);
            if (k > pc) {
                k -= pc; wrd = qq.z; w2 = 2; pc = __popc(qq.z);
                if (k > pc) { k -= pc; wrd = qq.w; w2 = 3; }
            }
        }
        // Fixed-depth 5-step binary select of the k-th set bit (1-indexed).
        int idx = 0;
        int cc = __popc(wrd & 0xFFFFu);
        if (k > cc) { k -= cc; idx += 16; wrd >>= 16; }
        cc = __popc(wrd & 0xFFu);
        if (k > cc) { k -= cc; idx += 8; wrd >>= 8; }
        cc = __popc(wrd & 0xFu);
        if (k > cc) { k -= cc; idx += 4; wrd >>= 4; }
        cc = __popc(wrd & 0x3u);
        if (k > cc) { k -= cc; idx += 2; wrd >>= 2; }
        cc = wrd & 1u;
        if (k > cc) { idx += 1; }
        pos = lo * 1024 + (gi * 4 + w2) * 32 + idx;
    }

    float2 hw;
    hw.x = (float)(pos / WW);
    hw.y = (float)(pos & (WW - 1));
    *reinterpret_cast<float2*>(out + ((size_t)b * NUM + pt) * 2) = hw;

    // Tail fill ((H, W) tuple leaves flattened into d_out).
    if (blockIdx.x == 0) {
        for (int i = t; i < tail_n; i += 256) out[IDX_ELEMS + i] = 512.0f;
    }
}

extern "C" void kernel_launch(void* const* d_in, const int* in_sizes, int n_in,
                              void* d_out, int out_size) {
    // Identify inputs by size, robust to metadata ordering.
    const float* masks  = nullptr;   // [64,4,512,512] f32 -> 67,108,864 elems
    const float* rand_u = nullptr;   // [64,1024] f32      -> 65,536 elems
    for (int i = 0; i < n_in; i++) {
        if (in_sizes[i] == BB * NPLANES * HWPIX) masks = (const float*)d_in[i];
        else if (in_sizes[i] == BB * NUM)        rand_u = (const float*)d_in[i];
    }
    if (!masks)  masks  = (const float*)d_in[0];
    if (!rand_u) rand_u = (const float*)d_in[1];
    float* out = (float*)d_out;      // [64,1024,2] stored as float32 (+ tail)

    int tail_n = out_size - IDX_ELEMS;
    if (tail_n < 0) tail_n = 0;

    k_mask_bits<<<(BB * HW4) / 256, 256>>>(reinterpret_cast<const float4*>(masks));
    k_sample<<<BB * PARTS, 256>>>(rand_u, out, tail_n);
}